// round 2
// baseline (speedup 1.0000x reference)
#include <cuda_runtime.h>
#include <cstdint>

// ---------------------------------------------------------------------------
// Problem constants
// ---------------------------------------------------------------------------
#define kB 16
#define kH 8
#define kA 512
#define kC 359   /* A - int(A*0.3) = 512 - 153 */

// ---------------------------------------------------------------------------
// Scratch (device globals; no runtime allocation allowed)
// ---------------------------------------------------------------------------
__device__ float g_Qp[kB * kA * kA];       // (B, A, A)  Qp[b,j,i]
__device__ float g_Kp[kB * kA * kA];       // (B, A, A)  Kp[b,j,k]
__device__ float g_am0[kB * kA * kA];      // (B, A, A)  am0[b,i,k] (scaled by 1/sqrt(8))
__device__ float g_Vp[kB * kA];            // (B, A)
__device__ float g_out3[kB * kH * kA];     // (B, H, A) flattened as [bh*512 + i]
__device__ unsigned g_km[2];
__device__ int g_mutate;
__device__ int g_r1[kB * kH];
__device__ int g_r2[kB * kH];

// ---------------------------------------------------------------------------
// Threefry2x32 (exact JAX semantics)
// ---------------------------------------------------------------------------
__device__ __forceinline__ void tf2x32(unsigned k0, unsigned k1,
                                       unsigned x0, unsigned x1,
                                       unsigned &o0, unsigned &o1) {
    unsigned ks2 = k0 ^ k1 ^ 0x1BD11BDAu;
    x0 += k0; x1 += k1;
#define TF_R(r) { x0 += x1; x1 = __funnelshift_l(x1, x1, r); x1 ^= x0; }
    TF_R(13) TF_R(15) TF_R(26) TF_R(6)
    x0 += k1;  x1 += ks2 + 1u;
    TF_R(17) TF_R(29) TF_R(16) TF_R(24)
    x0 += ks2; x1 += k0 + 2u;
    TF_R(13) TF_R(15) TF_R(26) TF_R(6)
    x0 += k0;  x1 += k1 + 3u;
    TF_R(17) TF_R(29) TF_R(16) TF_R(24)
    x0 += k1;  x1 += ks2 + 4u;
    TF_R(13) TF_R(15) TF_R(26) TF_R(6)
    x0 += ks2; x1 += k0 + 5u;
#undef TF_R
    o0 = x0; o1 = x1;
}

__device__ __forceinline__ float unit_float(unsigned bits) {
    // bitcast((bits>>9)|0x3f800000) - 1.0  in [0,1)
    return __uint_as_float((bits >> 9) | 0x3f800000u) - 1.0f;
}

__device__ __forceinline__ float mut_factor(unsigned bits) {
    const float mn = 1.0f - 0.3f;
    const float mx = 1.0f + 0.3f;
    float f = unit_float(bits);
    return fmaxf(mn, f * (mx - mn) + mn);
}

__device__ __forceinline__ float warpMax(float v) {
#pragma unroll
    for (int o = 16; o > 0; o >>= 1) v = fmaxf(v, __shfl_xor_sync(0xffffffffu, v, o));
    return v;
}
__device__ __forceinline__ float warpSum(float v) {
#pragma unroll
    for (int o = 16; o > 0; o >>= 1) v += __shfl_xor_sync(0xffffffffu, v, o);
    return v;
}

// ---------------------------------------------------------------------------
// PRNG setup: derive all keys/constants deterministically (partitionable
// threefry semantics: split is fold-like, random_bits(32) = o0 ^ o1 of
// threefry(key, hi(i), lo(i)) over a uint64 iota).
// 128 threads: thread t computes r1[t], r2[t]; thread 0 stores km + branch.
// ---------------------------------------------------------------------------
__global__ void setup_kernel() {
    const int tid = threadIdx.x;       // 0..127
    unsigned kp0, kp1, km0, km1, kr10, kr11, kr20, kr21;
    // split(key(42), 4) fold-like: key_i = threefry((0,42), 0, i)
    tf2x32(0u, 42u, 0u, 0u, kp0, kp1);
    tf2x32(0u, 42u, 0u, 1u, km0, km1);
    tf2x32(0u, 42u, 0u, 2u, kr10, kr11);
    tf2x32(0u, 42u, 0u, 3u, kr20, kr21);

    if (tid == 0) {
        g_km[0] = km0; g_km[1] = km1;
        unsigned o0, o1;
        tf2x32(kp0, kp1, 0u, 0u, o0, o1);        // uniform(kp, ()) bits
        float p = unit_float(o0 ^ o1);
        g_mutate = (p <= 0.6f) ? 1 : 0;
    }

    // randint(kr, (16,8), 0, 512): multiplier = (2^16 % 512)^2 % 512 = 0,
    // so result = lower_bits % 512 with lower key = split(kr)[1] = tf(kr,0,1).
    unsigned a0, a1, o0, o1;
    tf2x32(kr10, kr11, 0u, 1u, a0, a1);
    tf2x32(a0, a1, 0u, (unsigned)tid, o0, o1);
    g_r1[tid] = (int)((o0 ^ o1) & 511u);

    tf2x32(kr20, kr21, 0u, 1u, a0, a1);
    tf2x32(a0, a1, 0u, (unsigned)tid, o0, o1);
    g_r2[tid] = (int)((o0 ^ o1) & 511u);
}

// ---------------------------------------------------------------------------
// GEMM (NT): C[m,n] = sum_k A[m,k]*W[n,k] + bias[n].  M=8192, N=K=512.
// dst: 0 -> g_Qp, 1 -> g_Kp.  64x64 tile, BK=16, 256 threads, 4x4/thread.
// ---------------------------------------------------------------------------
__global__ void gemm_nt(const float* __restrict__ Ag, const float* __restrict__ W,
                        const float* __restrict__ bias, int dst) {
    __shared__ float As[16][64];
    __shared__ float Bs[16][64];
    float* C = dst ? g_Kp : g_Qp;
    const int tid = threadIdx.x;
    const int m0 = blockIdx.y * 64;
    const int n0 = blockIdx.x * 64;
    const int tn = tid & 15, tm = tid >> 4;
    float acc[4][4];
#pragma unroll
    for (int y = 0; y < 4; y++)
#pragma unroll
        for (int x = 0; x < 4; x++) acc[y][x] = 0.f;

    for (int k0 = 0; k0 < 512; k0 += 16) {
#pragma unroll
        for (int l = 0; l < 4; l++) {
            int idx = tid + l * 256;
            int r = idx >> 4, c = idx & 15;
            As[c][r] = Ag[(m0 + r) * 512 + (k0 + c)];
            Bs[c][r] = W[(n0 + r) * 512 + (k0 + c)];
        }
        __syncthreads();
#pragma unroll
        for (int kk = 0; kk < 16; kk++) {
            float4 av = *reinterpret_cast<const float4*>(&As[kk][tm * 4]);
            float4 bv = *reinterpret_cast<const float4*>(&Bs[kk][tn * 4]);
            float a4[4] = {av.x, av.y, av.z, av.w};
            float b4[4] = {bv.x, bv.y, bv.z, bv.w};
#pragma unroll
            for (int y = 0; y < 4; y++)
#pragma unroll
                for (int x = 0; x < 4; x++) acc[y][x] += a4[y] * b4[x];
        }
        __syncthreads();
    }
#pragma unroll
    for (int y = 0; y < 4; y++) {
        int m = m0 + tm * 4 + y;
        float4 o;
        o.x = acc[y][0] + bias[n0 + tn * 4 + 0];
        o.y = acc[y][1] + bias[n0 + tn * 4 + 1];
        o.z = acc[y][2] + bias[n0 + tn * 4 + 2];
        o.w = acc[y][3] + bias[n0 + tn * 4 + 3];
        *reinterpret_cast<float4*>(&C[m * 512 + n0 + tn * 4]) = o;
    }
}

// ---------------------------------------------------------------------------
// Batched TN GEMM: am0[z,i,n] = (1/sqrt(8)) * sum_j Qp[z,j,i] * Kp[z,j,n]
// ---------------------------------------------------------------------------
__global__ void gemm_tn(void) {
    __shared__ float As[16][64];
    __shared__ float Bs[16][64];
    const int tid = threadIdx.x;
    const int i0 = blockIdx.y * 64;
    const int n0 = blockIdx.x * 64;
    const int z = blockIdx.z;
    const float* Qb = g_Qp + z * kA * kA;
    const float* Kb = g_Kp + z * kA * kA;
    const int tn = tid & 15, tm = tid >> 4;
    float acc[4][4];
#pragma unroll
    for (int y = 0; y < 4; y++)
#pragma unroll
        for (int x = 0; x < 4; x++) acc[y][x] = 0.f;

    for (int j0 = 0; j0 < 512; j0 += 16) {
#pragma unroll
        for (int l = 0; l < 4; l++) {
            int idx = tid + l * 256;
            int jj = idx >> 6, ii = idx & 63;
            As[jj][ii] = Qb[(j0 + jj) * 512 + i0 + ii];
            Bs[jj][ii] = Kb[(j0 + jj) * 512 + n0 + ii];
        }
        __syncthreads();
#pragma unroll
        for (int kk = 0; kk < 16; kk++) {
            float4 av = *reinterpret_cast<const float4*>(&As[kk][tm * 4]);
            float4 bv = *reinterpret_cast<const float4*>(&Bs[kk][tn * 4]);
            float a4[4] = {av.x, av.y, av.z, av.w};
            float b4[4] = {bv.x, bv.y, bv.z, bv.w};
#pragma unroll
            for (int y = 0; y < 4; y++)
#pragma unroll
                for (int x = 0; x < 4; x++) acc[y][x] += a4[y] * b4[x];
        }
        __syncthreads();
    }
    const float inv = 1.0f / sqrtf(8.0f);
    float* C = g_am0 + z * kA * kA;
#pragma unroll
    for (int y = 0; y < 4; y++) {
        int m = i0 + tm * 4 + y;
        float4 o;
        o.x = acc[y][0] * inv;
        o.y = acc[y][1] * inv;
        o.z = acc[y][2] * inv;
        o.w = acc[y][3] * inv;
        *reinterpret_cast<float4*>(&C[m * 512 + n0 + tn * 4]) = o;
    }
}

// ---------------------------------------------------------------------------
// Vp[b,i] = sum_k V[b,k]*WVw[i,k] + bv[i].  warp per (b,i).
// ---------------------------------------------------------------------------
__global__ void vp_kernel(const float* __restrict__ V, const float* __restrict__ Wv,
                          const float* __restrict__ bv) {
    int w = threadIdx.x >> 5, lane = threadIdx.x & 31;
    int i = blockIdx.x * 8 + w;
    int b = blockIdx.y;
    float acc = 0.f;
    for (int k = lane; k < 512; k += 32)
        acc += V[b * 512 + k] * Wv[i * 512 + k];
    acc = warpSum(acc);
    if (lane == 0) g_Vp[b * 512 + i] = acc + bv[i];
}

// ---------------------------------------------------------------------------
// Fused mutate/crossover + softmax + V contraction.
// Block (256 thr) per (i, bh) row of the (B,H,A,A) attention matrix.
// Mutation factors regenerated via threefry (partitionable scheme):
//   bits(idx) = o0 ^ o1 of threefry(km, 0, idx), idx = (bh*512+i)*512+j.
// ---------------------------------------------------------------------------
__global__ void fused_kernel(void) {
    const int i  = blockIdx.x;          // 0..511
    const int bh = blockIdx.y;          // 0..127
    const int t  = threadIdx.x;         // 0..255
    const int b  = bh >> 3;
    const int lane = t & 31, wid = t >> 5;

    const float* rowN = g_am0 + (b * kA + i) * kA;
    const float* rowT = rowN;
    const int mut = g_mutate;
    if (!mut) {
        int r1 = g_r1[bh], r2 = g_r2[bh];
        int src = (i == r1) ? r2 : (i == r2) ? r1 : i;
        rowT = g_am0 + (b * kA + src) * kA;
    }
    const int j0 = t, j1 = t + 256;
    float v0 = (mut || j0 < kC) ? rowN[j0] : rowT[j0];
    float v1 = (mut || j1 < kC) ? rowN[j1] : rowT[j1];
    if (mut) {
        unsigned km0 = g_km[0], km1 = g_km[1];
        unsigned base = ((unsigned)bh * kA + (unsigned)i) * kA;
        unsigned o0, o1;
        tf2x32(km0, km1, 0u, base + (unsigned)j0, o0, o1);
        v0 *= mut_factor(o0 ^ o1);
        tf2x32(km0, km1, 0u, base + (unsigned)j1, o0, o1);
        v1 *= mut_factor(o0 ^ o1);
    }

    __shared__ float redM[8], redS[8], redD[8];
    float pm = warpMax(fmaxf(v0, v1));
    if (lane == 0) redM[wid] = pm;
    __syncthreads();
    float mx = redM[0];
#pragma unroll
    for (int q = 1; q < 8; q++) mx = fmaxf(mx, redM[q]);

    float e0 = expf(v0 - mx), e1 = expf(v1 - mx);
    float vp0 = g_Vp[b * kA + j0], vp1 = g_Vp[b * kA + j1];
    float s = warpSum(e0 + e1);
    float d = warpSum(e0 * vp0 + e1 * vp1);
    if (lane == 0) { redS[wid] = s; redD[wid] = d; }
    __syncthreads();
    if (t == 0) {
        float S = 0.f, D = 0.f;
#pragma unroll
        for (int q = 0; q < 8; q++) { S += redS[q]; D += redD[q]; }
        g_out3[bh * kA + i] = D / S;
    }
}

// ---------------------------------------------------------------------------
// y[b,o] = sum_x out2d[b,x] * WOw[o,x] + WOb[o],  x = h*512+i (same layout
// as g_out3 flattened).  Warp per (b,o), float4 loads.
// ---------------------------------------------------------------------------
__global__ void out_proj(const float* __restrict__ WOw, const float* __restrict__ WOb,
                         float* __restrict__ y) {
    int w = threadIdx.x >> 5, lane = threadIdx.x & 31;
    int o = blockIdx.x * 8 + w;
    int b = blockIdx.y;
    const float4* wv = reinterpret_cast<const float4*>(WOw + (size_t)o * 4096);
    const float4* xv = reinterpret_cast<const float4*>(g_out3 + b * 4096);
    float acc = 0.f;
    for (int it = lane; it < 1024; it += 32) {
        float4 w4 = wv[it], x4 = xv[it];
        acc += w4.x * x4.x + w4.y * x4.y + w4.z * x4.z + w4.w * x4.w;
    }
    acc = warpSum(acc);
    if (lane == 0) y[b * 512 + o] = acc + WOb[o];
}

// ---------------------------------------------------------------------------
// Launch
// ---------------------------------------------------------------------------
extern "C" void kernel_launch(void* const* d_in, const int* in_sizes, int n_in,
                              void* d_out, int out_size) {
    const float* Q   = (const float*)d_in[0];
    const float* K   = (const float*)d_in[1];
    const float* V   = (const float*)d_in[2];
    const float* WQw = (const float*)d_in[3];
    const float* WQb = (const float*)d_in[4];
    const float* WKw = (const float*)d_in[5];
    const float* WKb = (const float*)d_in[6];
    const float* WVw = (const float*)d_in[7];
    const float* WVb = (const float*)d_in[8];
    const float* WOw = (const float*)d_in[9];
    const float* WOb = (const float*)d_in[10];
    float* y = (float*)d_out;

    setup_kernel<<<1, 128>>>();
    gemm_nt<<<dim3(8, 128), 256>>>(Q, WQw, WQb, 0);           // Qp
    gemm_nt<<<dim3(8, 128), 256>>>(K, WKw, WKb, 1);           // Kp
    vp_kernel<<<dim3(64, 16), 256>>>(V, WVw, WVb);            // Vp
    gemm_tn<<<dim3(8, 8, 16), 256>>>();                       // am0 (scaled)
    fused_kernel<<<dim3(512, 128), 256>>>();                  // mutate/xover+softmax+V
    out_proj<<<dim3(64, 16), 256>>>(WOw, WOb, y);             // final projection
}

// round 3
// speedup vs baseline: 1.2643x; 1.2643x over previous
#include <cuda_runtime.h>
#include <cstdint>

// ---------------------------------------------------------------------------
// Problem constants
// ---------------------------------------------------------------------------
#define kB 16
#define kH 8
#define kA 512
#define kC 359   /* A - int(A*0.3) = 512 - 153 */

// ---------------------------------------------------------------------------
// Scratch (device globals; no runtime allocation allowed)
// ---------------------------------------------------------------------------
__device__ float g_Qp[kB * kA * kA];       // (B, A, A)  Qp[b,j,i]
__device__ float g_Kp[kB * kA * kA];       // (B, A, A)  Kp[b,j,k]
__device__ float g_am0[kB * kA * kA];      // (B, A, A)  am0[b,i,k] (scaled)
__device__ float g_Vp[kB * kA];            // (B, A)
__device__ float g_out3[kB * kH * kA];     // (B, H, A) flattened [bh*512 + i]
__device__ unsigned g_km[2];
__device__ int g_mutate;
__device__ int g_r1[kB * kH];
__device__ int g_r2[kB * kH];

// ---------------------------------------------------------------------------
// Threefry2x32 (exact JAX partitionable semantics)
// ---------------------------------------------------------------------------
__device__ __forceinline__ void tf2x32(unsigned k0, unsigned k1,
                                       unsigned x0, unsigned x1,
                                       unsigned &o0, unsigned &o1) {
    unsigned ks2 = k0 ^ k1 ^ 0x1BD11BDAu;
    x0 += k0; x1 += k1;
#define TF_R(r) { x0 += x1; x1 = __funnelshift_l(x1, x1, r); x1 ^= x0; }
    TF_R(13) TF_R(15) TF_R(26) TF_R(6)
    x0 += k1;  x1 += ks2 + 1u;
    TF_R(17) TF_R(29) TF_R(16) TF_R(24)
    x0 += ks2; x1 += k0 + 2u;
    TF_R(13) TF_R(15) TF_R(26) TF_R(6)
    x0 += k0;  x1 += k1 + 3u;
    TF_R(17) TF_R(29) TF_R(16) TF_R(24)
    x0 += k1;  x1 += ks2 + 4u;
    TF_R(13) TF_R(15) TF_R(26) TF_R(6)
    x0 += ks2; x1 += k0 + 5u;
#undef TF_R
    o0 = x0; o1 = x1;
}

__device__ __forceinline__ float unit_float(unsigned bits) {
    return __uint_as_float((bits >> 9) | 0x3f800000u) - 1.0f;
}
__device__ __forceinline__ float mut_factor(unsigned bits) {
    const float mn = 0.7f, mx = 1.3f;
    float f = unit_float(bits);
    return fmaxf(mn, f * (mx - mn) + mn);
}
__device__ __forceinline__ float warpSum(float v) {
#pragma unroll
    for (int o = 16; o > 0; o >>= 1) v += __shfl_xor_sync(0xffffffffu, v, o);
    return v;
}

// ---------------------------------------------------------------------------
// PRNG setup (unchanged — verified exact in round 1)
// ---------------------------------------------------------------------------
__global__ void setup_kernel() {
    const int tid = threadIdx.x;       // 0..127
    unsigned kp0, kp1, km0, km1, kr10, kr11, kr20, kr21;
    tf2x32(0u, 42u, 0u, 0u, kp0, kp1);
    tf2x32(0u, 42u, 0u, 1u, km0, km1);
    tf2x32(0u, 42u, 0u, 2u, kr10, kr11);
    tf2x32(0u, 42u, 0u, 3u, kr20, kr21);

    if (tid == 0) {
        g_km[0] = km0; g_km[1] = km1;
        unsigned o0, o1;
        tf2x32(kp0, kp1, 0u, 0u, o0, o1);
        float p = unit_float(o0 ^ o1);
        g_mutate = (p <= 0.6f) ? 1 : 0;
    }
    unsigned a0, a1, o0, o1;
    tf2x32(kr10, kr11, 0u, 1u, a0, a1);
    tf2x32(a0, a1, 0u, (unsigned)tid, o0, o1);
    g_r1[tid] = (int)((o0 ^ o1) & 511u);

    tf2x32(kr20, kr21, 0u, 1u, a0, a1);
    tf2x32(a0, a1, 0u, (unsigned)tid, o0, o1);
    g_r2[tid] = (int)((o0 ^ o1) & 511u);
}

// ---------------------------------------------------------------------------
// tf32 split-compensated MMA GEMM.
// C[m,n] = scale * sum_k A[m,k]*B[n,k] (+ bias[n])
// KMAJOR=false: A stored [m,512] row-major, B stored [n,512] row-major (GEMM1)
// KMAJOR=true : A stored [k,512] (A[m,k]=Ag[k*512+m]), B stored [k,512] (GEMM2)
// K = 512, lda=ldb=ldc=512.  Block tile 128x128, BK=8, 256 threads (8 warps 2x4).
// Each float split a = a_hi + a_lo (13-bit truncation); 3 mmas: hh + hl + lh.
// ---------------------------------------------------------------------------
__device__ __forceinline__ float trunc13(float x) {
    return __uint_as_float(__float_as_uint(x) & 0xFFFFE000u);
}

__device__ __forceinline__ void mma_tf32(float c[4], unsigned a0, unsigned a1,
                                         unsigned a2, unsigned a3,
                                         unsigned b0, unsigned b1) {
    asm volatile(
        "mma.sync.aligned.m16n8k8.row.col.f32.tf32.tf32.f32 "
        "{%0,%1,%2,%3}, {%4,%5,%6,%7}, {%8,%9}, {%0,%1,%2,%3};\n"
        : "+f"(c[0]), "+f"(c[1]), "+f"(c[2]), "+f"(c[3])
        : "r"(a0), "r"(a1), "r"(a2), "r"(a3), "r"(b0), "r"(b1));
}

template <bool KMAJOR>
__global__ __launch_bounds__(256)
void mma_gemm(const float* __restrict__ Ag, const float* __restrict__ Bg,
              const float* __restrict__ bias, float* __restrict__ Cg,
              float scale, int batchStride) {
    __shared__ float Ash[2][8][136];
    __shared__ float Asl[2][8][136];
    __shared__ float Bsh[2][8][136];
    __shared__ float Bsl[2][8][136];

    const int t = threadIdx.x;
    const int z = blockIdx.z;
    const float* A = Ag + (size_t)z * batchStride;
    const float* B = Bg + (size_t)z * batchStride;
    float* C = Cg + (size_t)z * batchStride;
    const int n0 = blockIdx.x * 128;
    const int m0 = blockIdx.y * 128;

    const int lane = t & 31, gid = lane >> 2, tig = lane & 3;
    const int wid = t >> 5;
    const int wm = (wid >> 2) * 64;   // 0 or 64
    const int wn = (wid & 3) * 32;    // 0,32,64,96

    float c[4][4][4];
#pragma unroll
    for (int mi = 0; mi < 4; mi++)
#pragma unroll
        for (int ni = 0; ni < 4; ni++)
#pragma unroll
            for (int r = 0; r < 4; r++) c[mi][ni][r] = 0.f;

    // per-thread global load coords
    float4 ra, rb;
    int lm, lkq;      // !KMAJOR
    int lkk, li4;     // KMAJOR
    if (!KMAJOR) { lm = t & 127; lkq = t >> 7; }
    else         { lkk = t >> 5; li4 = (t & 31) * 4; }

    auto gload = [&](int k0) {
        if (!KMAJOR) {
            ra = *reinterpret_cast<const float4*>(A + (size_t)(m0 + lm) * 512 + k0 + lkq * 4);
            rb = *reinterpret_cast<const float4*>(B + (size_t)(n0 + lm) * 512 + k0 + lkq * 4);
        } else {
            ra = *reinterpret_cast<const float4*>(A + (size_t)(k0 + lkk) * 512 + m0 + li4);
            rb = *reinterpret_cast<const float4*>(B + (size_t)(k0 + lkk) * 512 + n0 + li4);
        }
    };
    auto stsm = [&](int buf) {
        if (!KMAJOR) {
            float va[4] = {ra.x, ra.y, ra.z, ra.w};
            float vb[4] = {rb.x, rb.y, rb.z, rb.w};
#pragma unroll
            for (int j = 0; j < 4; j++) {
                float h = trunc13(va[j]);
                Ash[buf][lkq * 4 + j][lm] = h;
                Asl[buf][lkq * 4 + j][lm] = va[j] - h;
                h = trunc13(vb[j]);
                Bsh[buf][lkq * 4 + j][lm] = h;
                Bsl[buf][lkq * 4 + j][lm] = vb[j] - h;
            }
        } else {
            float4 h4, l4;
            h4.x = trunc13(ra.x); h4.y = trunc13(ra.y); h4.z = trunc13(ra.z); h4.w = trunc13(ra.w);
            l4.x = ra.x - h4.x; l4.y = ra.y - h4.y; l4.z = ra.z - h4.z; l4.w = ra.w - h4.w;
            *reinterpret_cast<float4*>(&Ash[buf][lkk][li4]) = h4;
            *reinterpret_cast<float4*>(&Asl[buf][lkk][li4]) = l4;
            h4.x = trunc13(rb.x); h4.y = trunc13(rb.y); h4.z = trunc13(rb.z); h4.w = trunc13(rb.w);
            l4.x = rb.x - h4.x; l4.y = rb.y - h4.y; l4.z = rb.z - h4.z; l4.w = rb.w - h4.w;
            *reinterpret_cast<float4*>(&Bsh[buf][lkk][li4]) = h4;
            *reinterpret_cast<float4*>(&Bsl[buf][lkk][li4]) = l4;
        }
    };

    gload(0);
    stsm(0);
    __syncthreads();

    for (int ks = 0; ks < 64; ks++) {
        const int buf = ks & 1;
        if (ks < 63) gload((ks + 1) * 8);

        unsigned ah[4][4], al[4][4], bh[4][2], bl[4][2];
#pragma unroll
        for (int mi = 0; mi < 4; mi++) {
            int r0 = wm + mi * 16 + gid;
            int r1 = r0 + 8;
            ah[mi][0] = __float_as_uint(Ash[buf][tig][r0]);
            ah[mi][1] = __float_as_uint(Ash[buf][tig][r1]);
            ah[mi][2] = __float_as_uint(Ash[buf][tig + 4][r0]);
            ah[mi][3] = __float_as_uint(Ash[buf][tig + 4][r1]);
            al[mi][0] = __float_as_uint(Asl[buf][tig][r0]);
            al[mi][1] = __float_as_uint(Asl[buf][tig][r1]);
            al[mi][2] = __float_as_uint(Asl[buf][tig + 4][r0]);
            al[mi][3] = __float_as_uint(Asl[buf][tig + 4][r1]);
        }
#pragma unroll
        for (int ni = 0; ni < 4; ni++) {
            int cn = wn + ni * 8 + gid;
            bh[ni][0] = __float_as_uint(Bsh[buf][tig][cn]);
            bh[ni][1] = __float_as_uint(Bsh[buf][tig + 4][cn]);
            bl[ni][0] = __float_as_uint(Bsl[buf][tig][cn]);
            bl[ni][1] = __float_as_uint(Bsl[buf][tig + 4][cn]);
        }
#pragma unroll
        for (int mi = 0; mi < 4; mi++)
#pragma unroll
            for (int ni = 0; ni < 4; ni++) {
                mma_tf32(c[mi][ni], ah[mi][0], ah[mi][1], ah[mi][2], ah[mi][3],
                         bh[ni][0], bh[ni][1]);
                mma_tf32(c[mi][ni], ah[mi][0], ah[mi][1], ah[mi][2], ah[mi][3],
                         bl[ni][0], bl[ni][1]);
                mma_tf32(c[mi][ni], al[mi][0], al[mi][1], al[mi][2], al[mi][3],
                         bh[ni][0], bh[ni][1]);
            }
        if (ks < 63) {
            stsm(buf ^ 1);
            __syncthreads();
        }
    }

    // epilogue
#pragma unroll
    for (int mi = 0; mi < 4; mi++) {
#pragma unroll
        for (int ni = 0; ni < 4; ni++) {
            int row = m0 + wm + mi * 16 + gid;
            int col = n0 + wn + ni * 8 + 2 * tig;
            float b0v = 0.f, b1v = 0.f;
            if (bias) { b0v = bias[col]; b1v = bias[col + 1]; }
            float2 o0, o1;
            o0.x = c[mi][ni][0] * scale + b0v;
            o0.y = c[mi][ni][1] * scale + b1v;
            o1.x = c[mi][ni][2] * scale + b0v;
            o1.y = c[mi][ni][3] * scale + b1v;
            *reinterpret_cast<float2*>(&C[(size_t)row * 512 + col]) = o0;
            *reinterpret_cast<float2*>(&C[(size_t)(row + 8) * 512 + col]) = o1;
        }
    }
}

// ---------------------------------------------------------------------------
// Vp[b,i] = sum_k V[b,k]*WVw[i,k] + bv[i].  Warp per i; W row in registers,
// looped over all 16 b (W read once).
// ---------------------------------------------------------------------------
__global__ void vp_kernel(const float* __restrict__ V, const float* __restrict__ Wv,
                          const float* __restrict__ bv) {
    int wid = threadIdx.x >> 5, lane = threadIdx.x & 31;
    int i = blockIdx.x * 8 + wid;
    float w[16];
#pragma unroll
    for (int cc = 0; cc < 16; cc++) w[cc] = Wv[i * 512 + lane + 32 * cc];
    float bvi = bv[i];
    for (int b = 0; b < kB; b++) {
        float acc = 0.f;
#pragma unroll
        for (int cc = 0; cc < 16; cc++) acc += w[cc] * V[b * 512 + lane + 32 * cc];
        acc = warpSum(acc);
        if (lane == 0) g_Vp[b * 512 + i] = acc + bvi;
    }
}

// ---------------------------------------------------------------------------
// Fused mutate/crossover + softmax + V contraction, ALL 8 HEADS per block.
// Block (512 thr) per (i, b): row am0[b,i,:] loaded ONCE (8x traffic cut).
// No max-subtraction (logits bounded ~|9|, exp safe in fp32).
// ---------------------------------------------------------------------------
__global__ __launch_bounds__(512)
void fused_kernel(void) {
    const int i = blockIdx.x;           // 0..511
    const int b = blockIdx.y;           // 0..15
    const int j = threadIdx.x;          // 0..511
    const int lane = j & 31, wid = j >> 5;

    const float v  = g_am0[(b * kA + i) * kA + j];
    const float vp = g_Vp[b * kA + j];
    float e[8];

    if (g_mutate) {
        const unsigned km0 = g_km[0], km1 = g_km[1];
        unsigned idx = ((unsigned)(b * 8) << 18) + ((unsigned)i << 9) + (unsigned)j;
#pragma unroll
        for (int h = 0; h < 8; h++) {
            unsigned o0, o1;
            tf2x32(km0, km1, 0u, idx, o0, o1);
            e[h] = __expf(v * mut_factor(o0 ^ o1));
            idx += (1u << 18);
        }
    } else {
#pragma unroll
        for (int h = 0; h < 8; h++) {
            int bh = b * 8 + h;
            int r1 = g_r1[bh], r2 = g_r2[bh];
            int src = (i == r1) ? r2 : (i == r2) ? r1 : i;
            float vh = v;
            if (j >= kC && src != i) vh = g_am0[(b * kA + src) * kA + j];
            e[h] = __expf(vh);
        }
    }

    __shared__ float rS[8][16], rD[8][16];
#pragma unroll
    for (int h = 0; h < 8; h++) {
        float s = warpSum(e[h]);
        float d = warpSum(e[h] * vp);
        if (lane == 0) { rS[h][wid] = s; rD[h][wid] = d; }
    }
    __syncthreads();
    if (j < 8) {
        float S = 0.f, D = 0.f;
#pragma unroll
        for (int w = 0; w < 16; w++) { S += rS[j][w]; D += rD[j][w]; }
        g_out3[(b * 8 + j) * kA + i] = D / S;
    }
}

// ---------------------------------------------------------------------------
// y[b,o] = sum_x g_out3[b*4096+x] * WOw[o,x] + WOb[o].
// Grid 16 blocks x 32 o's; x tiles staged in smem; WOw streamed exactly once.
// Thread t: o_l = t>>3 (0..31), bq = t&7 -> handles b=bq and b=bq+8.
// ---------------------------------------------------------------------------
__global__ __launch_bounds__(256)
void out_proj(const float* __restrict__ WOw, const float* __restrict__ WOb,
              float* __restrict__ y) {
    __shared__ float xs[16][516];
    const int t = threadIdx.x;
    const int o_l = t >> 3, bq = t & 7;
    const int o = blockIdx.x * 32 + o_l;
    float acc0 = 0.f, acc1 = 0.f;

    for (int ch = 0; ch < 8; ch++) {
        // stage x chunk: 16 rows x 512 cols
#pragma unroll
        for (int l = 0; l < 8; l++) {
            int idx = t + l * 256;            // 0..2047 float4 units
            int row = idx >> 7, c4 = idx & 127;
            float4 v = *reinterpret_cast<const float4*>(
                g_out3 + row * 4096 + ch * 512 + c4 * 4);
            *reinterpret_cast<float4*>(&xs[row][c4 * 4]) = v;
        }
        __syncthreads();
        const float4* Wp = reinterpret_cast<const float4*>(WOw + (size_t)o * 4096 + ch * 512);
#pragma unroll 8
        for (int k4 = 0; k4 < 128; k4++) {
            float4 w4 = Wp[k4];
            float4 x0 = *reinterpret_cast<const float4*>(&xs[bq][k4 * 4]);
            float4 x1 = *reinterpret_cast<const float4*>(&xs[bq + 8][k4 * 4]);
            acc0 += w4.x * x0.x + w4.y * x0.y + w4.z * x0.z + w4.w * x0.w;
            acc1 += w4.x * x1.x + w4.y * x1.y + w4.z * x1.z + w4.w * x1.w;
        }
        __syncthreads();
    }
    float bo = WOb[o];
    y[bq * 512 + o] = acc0 + bo;
    y[(bq + 8) * 512 + o] = acc1 + bo;
}

// ---------------------------------------------------------------------------
// Launch (fused_kernel is 6th launch -> captured by ncu -s 5 -c 1)
// ---------------------------------------------------------------------------
extern "C" void kernel_launch(void* const* d_in, const int* in_sizes, int n_in,
                              void* d_out, int out_size) {
    const float* Q   = (const float*)d_in[0];
    const float* K   = (const float*)d_in[1];
    const float* V   = (const float*)d_in[2];
    const float* WQw = (const float*)d_in[3];
    const float* WQb = (const float*)d_in[4];
    const float* WKw = (const float*)d_in[5];
    const float* WKb = (const float*)d_in[6];
    const float* WVw = (const float*)d_in[7];
    const float* WVb = (const float*)d_in[8];
    const float* WOw = (const float*)d_in[9];
    const float* WOb = (const float*)d_in[10];
    float* y = (float*)d_out;

    float* dQp;  cudaGetSymbolAddress((void**)&dQp,  g_Qp);
    float* dKp;  cudaGetSymbolAddress((void**)&dKp,  g_Kp);
    float* dam;  cudaGetSymbolAddress((void**)&dam,  g_am0);

    setup_kernel<<<1, 128>>>();
    vp_kernel<<<64, 256>>>(V, WVw, WVb);
    // Qp / Kp: M=8192, N=512 -> grid (4, 64)
    mma_gemm<false><<<dim3(4, 64, 1), 256>>>(Q, WQw, WQb, dQp, 1.0f, 0);
    mma_gemm<false><<<dim3(4, 64, 1), 256>>>(K, WKw, WKb, dKp, 1.0f, 0);
    // am0[z] = (1/sqrt8) Qp[z]^T Kp[z]: batched 512x512x512 -> grid (4, 4, 16)
    mma_gemm<true><<<dim3(4, 4, 16), 256>>>(dQp, dKp, nullptr, dam,
                                            1.0f / sqrtf(8.0f), kA * kA);
    fused_kernel<<<dim3(512, 16), 512>>>();
    out_proj<<<16, 256>>>(WOw, WOb, y);
}

// round 4
// speedup vs baseline: 1.5320x; 1.2117x over previous
#include <cuda_runtime.h>
#include <cstdint>

#define kB 16
#define kH 8
#define kA 512
#define kC 359   /* A - int(A*0.3) */

// ---------------------------------------------------------------------------
// Scratch (device globals)
// ---------------------------------------------------------------------------
__device__ float g_QpT[kB * kA * kA];      // (B, A, A)  QpT[b,i,j]  (j contiguous)
__device__ float g_KpT[kB * kA * kA];      // (B, A, A)  KpT[b,n,j]
__device__ float g_am0[kB * kA * kA];      // (B, A, A)  am0[b,i,n] (scaled)
__device__ float g_Vp[kB * kA];
__device__ float g_out3[kB * kH * kA];     // [bh*512 + i]
__device__ unsigned g_km[2];
__device__ int g_mutate;
__device__ int g_r1[kB * kH];
__device__ int g_r2[kB * kH];

// ---------------------------------------------------------------------------
// Threefry2x32 (exact JAX partitionable semantics) — verified R1/R2
// ---------------------------------------------------------------------------
__device__ __forceinline__ void tf2x32(unsigned k0, unsigned k1,
                                       unsigned x0, unsigned x1,
                                       unsigned &o0, unsigned &o1) {
    unsigned ks2 = k0 ^ k1 ^ 0x1BD11BDAu;
    x0 += k0; x1 += k1;
#define TF_R(r) { x0 += x1; x1 = __funnelshift_l(x1, x1, r); x1 ^= x0; }
    TF_R(13) TF_R(15) TF_R(26) TF_R(6)
    x0 += k1;  x1 += ks2 + 1u;
    TF_R(17) TF_R(29) TF_R(16) TF_R(24)
    x0 += ks2; x1 += k0 + 2u;
    TF_R(13) TF_R(15) TF_R(26) TF_R(6)
    x0 += k0;  x1 += k1 + 3u;
    TF_R(17) TF_R(29) TF_R(16) TF_R(24)
    x0 += k1;  x1 += ks2 + 4u;
    TF_R(13) TF_R(15) TF_R(26) TF_R(6)
    x0 += ks2; x1 += k0 + 5u;
#undef TF_R
    o0 = x0; o1 = x1;
}
__device__ __forceinline__ float unit_float(unsigned bits) {
    return __uint_as_float((bits >> 9) | 0x3f800000u) - 1.0f;
}
__device__ __forceinline__ float mut_factor(unsigned bits) {
    const float mn = 0.7f, mx = 1.3f;
    return fmaxf(mn, unit_float(bits) * (mx - mn) + mn);
}
__device__ __forceinline__ float warpSum(float v) {
#pragma unroll
    for (int o = 16; o > 0; o >>= 1) v += __shfl_xor_sync(0xffffffffu, v, o);
    return v;
}

__global__ void setup_kernel() {
    const int tid = threadIdx.x;       // 0..127
    unsigned kp0, kp1, km0, km1, kr10, kr11, kr20, kr21;
    tf2x32(0u, 42u, 0u, 0u, kp0, kp1);
    tf2x32(0u, 42u, 0u, 1u, km0, km1);
    tf2x32(0u, 42u, 0u, 2u, kr10, kr11);
    tf2x32(0u, 42u, 0u, 3u, kr20, kr21);
    if (tid == 0) {
        g_km[0] = km0; g_km[1] = km1;
        unsigned o0, o1;
        tf2x32(kp0, kp1, 0u, 0u, o0, o1);
        g_mutate = (unit_float(o0 ^ o1) <= 0.6f) ? 1 : 0;
    }
    unsigned a0, a1, o0, o1;
    tf2x32(kr10, kr11, 0u, 1u, a0, a1);
    tf2x32(a0, a1, 0u, (unsigned)tid, o0, o1);
    g_r1[tid] = (int)((o0 ^ o1) & 511u);
    tf2x32(kr20, kr21, 0u, 1u, a0, a1);
    tf2x32(a0, a1, 0u, (unsigned)tid, o0, o1);
    g_r2[tid] = (int)((o0 ^ o1) & 511u);
}

// ---------------------------------------------------------------------------
// tf32 split-compensated NT GEMM with ldmatrix fragment loads.
// C[m,n] = scale*sum_k A[m,k]*B[n,k] (+bias[n]); A,B row-major k-contiguous.
// OUT_T: write C transposed per 512-batch: out[(m>>9)*512*512 + n*512 + (m&511)]
// Tile 128x128, BK=8, 256 thr (8 warps 2x4). smem granule-swizzled [row][k].
// ---------------------------------------------------------------------------
__device__ __forceinline__ float trunc13(float x) {
    return __uint_as_float(__float_as_uint(x) & 0xFFFFE000u);
}
__device__ __forceinline__ void mma_tf32(float c[4], const uint32_t a[4],
                                         uint32_t b0, uint32_t b1) {
    asm volatile(
        "mma.sync.aligned.m16n8k8.row.col.f32.tf32.tf32.f32 "
        "{%0,%1,%2,%3}, {%4,%5,%6,%7}, {%8,%9}, {%0,%1,%2,%3};\n"
        : "+f"(c[0]), "+f"(c[1]), "+f"(c[2]), "+f"(c[3])
        : "r"(a[0]), "r"(a[1]), "r"(a[2]), "r"(a[3]), "r"(b0), "r"(b1));
}
__device__ __forceinline__ void ldsm4(uint32_t r[4], uint32_t saddr) {
    asm volatile("ldmatrix.sync.aligned.m8n8.x4.shared.b16 {%0,%1,%2,%3}, [%4];"
                 : "=r"(r[0]), "=r"(r[1]), "=r"(r[2]), "=r"(r[3]) : "r"(saddr));
}
// float-offset within a 1024-float slab for element (row, k): 16B granule swizzle
__device__ __forceinline__ int sw_off(int row, int kq) {
    return row * 8 + ((kq ^ ((row >> 2) & 1)) << 2);
}

template <bool OUT_T>
__global__ __launch_bounds__(256)
void gemm_nt(const float* __restrict__ Ag, const float* __restrict__ Bg,
             const float* __restrict__ bias, float* __restrict__ Cg,
             float scale) {
    __shared__ float sAh[2][1024], sAl[2][1024], sBh[2][1024], sBl[2][1024];
    const int t = threadIdx.x;
    const int z = blockIdx.z;
    const float* A = Ag + (size_t)z * (kA * kA);
    const float* B = Bg + (size_t)z * (kA * kA);
    float* C = Cg + (size_t)z * (kA * kA);
    const int n0 = blockIdx.x * 128;
    const int m0 = blockIdx.y * 128;

    const int lane = t & 31, wid = t >> 5;
    const int wm = (wid >> 2) * 64, wn = (wid & 3) * 32;
    const int gid = lane >> 2, tig = lane & 3;

    // writer coords: thread t covers (row = t&127, k-quad = t>>7)
    const int wrow = t & 127, wkq = t >> 7;
    const float* Aptr = A + (size_t)(m0 + wrow) * 512 + wkq * 4;
    const float* Bptr = B + (size_t)(n0 + wrow) * 512 + wkq * 4;
    const int wOff = sw_off(wrow, wkq);

    // ldmatrix source offsets (bytes) — q = lane>>3 selects sub-matrix
    const int q = lane >> 3, rr = lane & 7;
    int aOff[4], bOff[2];
#pragma unroll
    for (int mi = 0; mi < 4; mi++) {
        int m = wm + mi * 16 + (q & 1) * 8 + rr;
        aOff[mi] = sw_off(m, q >> 1) * 4;
    }
#pragma unroll
    for (int p = 0; p < 2; p++) {
        int nrow = wn + (p * 2 + (q >> 1)) * 8 + rr;
        bOff[p] = sw_off(nrow, q & 1) * 4;
    }
    const uint32_t bAh = (uint32_t)__cvta_generic_to_shared(&sAh[0][0]);
    const uint32_t bAl = (uint32_t)__cvta_generic_to_shared(&sAl[0][0]);
    const uint32_t bBh = (uint32_t)__cvta_generic_to_shared(&sBh[0][0]);
    const uint32_t bBl = (uint32_t)__cvta_generic_to_shared(&sBl[0][0]);

    float c[4][4][4];
#pragma unroll
    for (int mi = 0; mi < 4; mi++)
#pragma unroll
        for (int ni = 0; ni < 4; ni++)
#pragma unroll
            for (int r = 0; r < 4; r++) c[mi][ni][r] = 0.f;

    float4 ra, rb;
    auto gload = [&](int k0) {
        ra = *reinterpret_cast<const float4*>(Aptr + k0);
        rb = *reinterpret_cast<const float4*>(Bptr + k0);
    };
    auto sts = [&](int buf) {
        float4 h, l;
        h.x = trunc13(ra.x); h.y = trunc13(ra.y); h.z = trunc13(ra.z); h.w = trunc13(ra.w);
        l.x = ra.x - h.x; l.y = ra.y - h.y; l.z = ra.z - h.z; l.w = ra.w - h.w;
        *reinterpret_cast<float4*>(&sAh[buf][wOff]) = h;
        *reinterpret_cast<float4*>(&sAl[buf][wOff]) = l;
        h.x = trunc13(rb.x); h.y = trunc13(rb.y); h.z = trunc13(rb.z); h.w = trunc13(rb.w);
        l.x = rb.x - h.x; l.y = rb.y - h.y; l.z = rb.z - h.z; l.w = rb.w - h.w;
        *reinterpret_cast<float4*>(&sBh[buf][wOff]) = h;
        *reinterpret_cast<float4*>(&sBl[buf][wOff]) = l;
    };

    gload(0);
    sts(0);
    __syncthreads();

    for (int ks = 0; ks < 64; ks++) {
        const int buf = ks & 1;
        const uint32_t bo = (uint32_t)buf * 4096u;
        if (ks < 63) gload((ks + 1) * 8);

        uint32_t ah[4][4], al[4][4], bh[2][4], bl[2][4];
#pragma unroll
        for (int mi = 0; mi < 4; mi++) ldsm4(ah[mi], bAh + bo + aOff[mi]);
#pragma unroll
        for (int mi = 0; mi < 4; mi++) ldsm4(al[mi], bAl + bo + aOff[mi]);
#pragma unroll
        for (int p = 0; p < 2; p++) ldsm4(bh[p], bBh + bo + bOff[p]);
#pragma unroll
        for (int p = 0; p < 2; p++) ldsm4(bl[p], bBl + bo + bOff[p]);

#pragma unroll
        for (int mi = 0; mi < 4; mi++)
#pragma unroll
            for (int ni = 0; ni < 4; ni++) {
                const int p = ni >> 1, s0 = (ni & 1) * 2;
                mma_tf32(c[mi][ni], ah[mi], bh[p][s0], bh[p][s0 + 1]);
                mma_tf32(c[mi][ni], ah[mi], bl[p][s0], bl[p][s0 + 1]);
                mma_tf32(c[mi][ni], al[mi], bh[p][s0], bh[p][s0 + 1]);
            }
        if (ks < 63) {
            sts(buf ^ 1);
            __syncthreads();
        }
    }

    // epilogue
#pragma unroll
    for (int mi = 0; mi < 4; mi++) {
#pragma unroll
        for (int ni = 0; ni < 4; ni++) {
            const int gm = m0 + wm + mi * 16 + gid;
            const int gc = n0 + wn + ni * 8 + 2 * tig;
            if (OUT_T) {
                const float bv0 = bias[gc], bv1 = bias[gc + 1];
                float* Cb = C + (size_t)(gm >> 9) * (kA * kA);
                const int j0 = gm & 511, j1 = (gm + 8) & 511;
                Cb[(size_t)gc * 512 + j0]       = c[mi][ni][0] + bv0;
                Cb[(size_t)(gc + 1) * 512 + j0] = c[mi][ni][1] + bv1;
                Cb[(size_t)gc * 512 + j1]       = c[mi][ni][2] + bv0;
                Cb[(size_t)(gc + 1) * 512 + j1] = c[mi][ni][3] + bv1;
            } else {
                float2 o0, o1;
                o0.x = c[mi][ni][0] * scale; o0.y = c[mi][ni][1] * scale;
                o1.x = c[mi][ni][2] * scale; o1.y = c[mi][ni][3] * scale;
                *reinterpret_cast<float2*>(&C[(size_t)gm * 512 + gc]) = o0;
                *reinterpret_cast<float2*>(&C[(size_t)(gm + 8) * 512 + gc]) = o1;
            }
        }
    }
}

// ---------------------------------------------------------------------------
// Vp[b,i] = sum_k V[b,k]*Wv[i,k] + bv[i].  Block per i (512), warp w -> b=w,w+8.
// ---------------------------------------------------------------------------
__global__ __launch_bounds__(256)
void vp_kernel(const float* __restrict__ V, const float* __restrict__ Wv,
               const float* __restrict__ bv) {
    const int i = blockIdx.x;
    const int w = threadIdx.x >> 5, lane = threadIdx.x & 31;
    const float* wr = Wv + (size_t)i * 512;
    float a0 = 0.f, a1 = 0.f;
#pragma unroll
    for (int cc = 0; cc < 4; cc++) {
        const int k = cc * 128 + lane * 4;
        float4 w4 = *reinterpret_cast<const float4*>(wr + k);
        float4 v0 = *reinterpret_cast<const float4*>(V + w * 512 + k);
        float4 v1 = *reinterpret_cast<const float4*>(V + (w + 8) * 512 + k);
        a0 += w4.x * v0.x + w4.y * v0.y + w4.z * v0.z + w4.w * v0.w;
        a1 += w4.x * v1.x + w4.y * v1.y + w4.z * v1.z + w4.w * v1.w;
    }
    a0 = warpSum(a0); a1 = warpSum(a1);
    if (lane == 0) {
        float b = bv[i];
        g_Vp[w * 512 + i] = a0 + b;
        g_Vp[(w + 8) * 512 + i] = a1 + b;
    }
}

// ---------------------------------------------------------------------------
// Fused mutate/crossover + softmax + V contraction.
// Block 256 thr per (i, b); warp h handles head h over all 512 j (16/lane).
// Row + Vp staged in smem once.
// ---------------------------------------------------------------------------
__global__ __launch_bounds__(256)
void fused_kernel(void) {
    const int i = blockIdx.x, b = blockIdx.y;
    const int t = threadIdx.x, lane = t & 31, h = t >> 5;
    __shared__ float sv[512], svp[512];

    if (t < 128)
        *reinterpret_cast<float4*>(&sv[t * 4]) =
            *reinterpret_cast<const float4*>(g_am0 + ((size_t)b * kA + i) * kA + t * 4);
    else
        *reinterpret_cast<float4*>(&svp[(t - 128) * 4]) =
            *reinterpret_cast<const float4*>(g_Vp + b * kA + (t - 128) * 4);
    __syncthreads();

    float s = 0.f, d = 0.f;
    if (g_mutate) {
        const unsigned km0 = g_km[0], km1 = g_km[1];
        const unsigned base = ((unsigned)(b * 8 + h) << 18) + ((unsigned)i << 9);
#pragma unroll 4
        for (int cc = 0; cc < 16; cc++) {
            const int j = cc * 32 + lane;
            unsigned o0, o1;
            tf2x32(km0, km1, 0u, base + (unsigned)j, o0, o1);
            const float e = __expf(sv[j] * mut_factor(o0 ^ o1));
            s += e; d += e * svp[j];
        }
    } else {
        const int bh = b * 8 + h;
        const int r1 = g_r1[bh], r2 = g_r2[bh];
        const int src = (i == r1) ? r2 : (i == r2) ? r1 : i;
        const float* srow = g_am0 + ((size_t)b * kA + src) * kA;
#pragma unroll 4
        for (int cc = 0; cc < 16; cc++) {
            const int j = cc * 32 + lane;
            const float v = (src == i || j < kC) ? sv[j] : srow[j];
            const float e = __expf(v);
            s += e; d += e * svp[j];
        }
    }
    s = warpSum(s); d = warpSum(d);
    if (lane == 0) g_out3[(b * 8 + h) * kA + i] = d / s;
}

// ---------------------------------------------------------------------------
// y[b,o] = sum_x g_out3[b*4096+x]*WOw[o,x] + WOb[o].  Grid 32 (16 o's each).
// ---------------------------------------------------------------------------
__global__ __launch_bounds__(256)
void out_proj(const float* __restrict__ WOw, const float* __restrict__ WOb,
              float* __restrict__ y) {
    __shared__ float xs[16][516];
    const int t = threadIdx.x;
    const int o_l = t >> 4, bq = t & 15;
    const int o = blockIdx.x * 16 + o_l;
    float acc = 0.f;

    for (int ch = 0; ch < 8; ch++) {
#pragma unroll
        for (int l = 0; l < 8; l++) {
            int idx = t + l * 256;               // 2048 float4 units
            int row = idx >> 7, c4 = idx & 127;
            *reinterpret_cast<float4*>(&xs[row][c4 * 4]) =
                *reinterpret_cast<const float4*>(g_out3 + row * 4096 + ch * 512 + c4 * 4);
        }
        __syncthreads();
        const float4* Wp = reinterpret_cast<const float4*>(WOw + (size_t)o * 4096 + ch * 512);
#pragma unroll 8
        for (int k4 = 0; k4 < 128; k4++) {
            float4 w4 = Wp[k4];
            float4 x4 = *reinterpret_cast<const float4*>(&xs[bq][k4 * 4]);
            acc += w4.x * x4.x + w4.y * x4.y + w4.z * x4.z + w4.w * x4.w;
        }
        __syncthreads();
    }
    y[bq * 512 + o] = acc + WOb[o];
}

// ---------------------------------------------------------------------------
// Launch (fused_kernel is launch #5 -> ncu -s 5 -c 1 captures it)
// ---------------------------------------------------------------------------
extern "C" void kernel_launch(void* const* d_in, const int* in_sizes, int n_in,
                              void* d_out, int out_size) {
    const float* Q   = (const float*)d_in[0];
    const float* K   = (const float*)d_in[1];
    const float* V   = (const float*)d_in[2];
    const float* WQw = (const float*)d_in[3];
    const float* WQb = (const float*)d_in[4];
    const float* WKw = (const float*)d_in[5];
    const float* WKb = (const float*)d_in[6];
    const float* WVw = (const float*)d_in[7];
    const float* WVb = (const float*)d_in[8];
    const float* WOw = (const float*)d_in[9];
    const float* WOb = (const float*)d_in[10];
    float* y = (float*)d_out;

    float* dQpT; cudaGetSymbolAddress((void**)&dQpT, g_QpT);
    float* dKpT; cudaGetSymbolAddress((void**)&dKpT, g_KpT);
    float* dam;  cudaGetSymbolAddress((void**)&dam,  g_am0);

    setup_kernel<<<1, 128>>>();
    vp_kernel<<<512, 256>>>(V, WVw, WVb);
    // Qp/Kp projections, output written pre-transposed: grid (N/128, M/128)
    gemm_nt<true><<<dim3(4, 64, 1), 256>>>(Q, WQw, WQb, dQpT, 1.0f);
    gemm_nt<true><<<dim3(4, 64, 1), 256>>>(K, WKw, WKb, dKpT, 1.0f);
    // am0[b] = (1/sqrt8) QpT[b] @ KpT[b]^T  (both row-major k-contiguous)
    gemm_nt<false><<<dim3(4, 4, 16), 256>>>(dQpT, dKpT, nullptr, dam,
                                            1.0f / sqrtf(8.0f));
    fused_kernel<<<dim3(512, 16), 256>>>();
    out_proj<<<32, 256>>>(WOw, WOb, y);
}

// round 5
// speedup vs baseline: 1.5763x; 1.0289x over previous
#include <cuda_runtime.h>
#include <cstdint>

#define kB 16
#define kH 8
#define kA 512
#define kC 359   /* A - int(A*0.3) */

// ---------------------------------------------------------------------------
// Scratch (device globals)
// ---------------------------------------------------------------------------
__device__ float g_QpT[kB * kA * kA];      // (B, A, A)  QpT[b,i,j] (j contiguous)
__device__ float g_KpT[kB * kA * kA];      // (B, A, A)  KpT[b,n,j]
__device__ float g_am0[kB * kA * kA];      // (B, A, A)  am0[b,i,n] (scaled)
__device__ float g_Vp[kB * kA];
__device__ float g_out3[kB * kH * kA];     // [bh*512 + i]

// ---------------------------------------------------------------------------
// Threefry2x32 — device version (mutation factors) + host version (keys)
// ---------------------------------------------------------------------------
__device__ __forceinline__ void tf2x32(unsigned k0, unsigned k1,
                                       unsigned x0, unsigned x1,
                                       unsigned &o0, unsigned &o1) {
    unsigned ks2 = k0 ^ k1 ^ 0x1BD11BDAu;
    x0 += k0; x1 += k1;
#define TF_R(r) { x0 += x1; x1 = __funnelshift_l(x1, x1, r); x1 ^= x0; }
    TF_R(13) TF_R(15) TF_R(26) TF_R(6)
    x0 += k1;  x1 += ks2 + 1u;
    TF_R(17) TF_R(29) TF_R(16) TF_R(24)
    x0 += ks2; x1 += k0 + 2u;
    TF_R(13) TF_R(15) TF_R(26) TF_R(6)
    x0 += k0;  x1 += k1 + 3u;
    TF_R(17) TF_R(29) TF_R(16) TF_R(24)
    x0 += k1;  x1 += ks2 + 4u;
    TF_R(13) TF_R(15) TF_R(26) TF_R(6)
    x0 += ks2; x1 += k0 + 5u;
#undef TF_R
    o0 = x0; o1 = x1;
}
__device__ __forceinline__ float unit_float(unsigned bits) {
    return __uint_as_float((bits >> 9) | 0x3f800000u) - 1.0f;
}
__device__ __forceinline__ float mut_factor(unsigned bits) {
    const float mn = 0.7f, mx = 1.3f;
    return fmaxf(mn, unit_float(bits) * (mx - mn) + mn);
}
__device__ __forceinline__ float warpSum(float v) {
#pragma unroll
    for (int o = 16; o > 0; o >>= 1) v += __shfl_xor_sync(0xffffffffu, v, o);
    return v;
}

static inline unsigned h_rotl(unsigned v, int r) { return (v << r) | (v >> (32 - r)); }
static void h_tf2x32(unsigned k0, unsigned k1, unsigned x0, unsigned x1,
                     unsigned &o0, unsigned &o1) {
    unsigned ks2 = k0 ^ k1 ^ 0x1BD11BDAu;
    x0 += k0; x1 += k1;
#define TH_R(r) { x0 += x1; x1 = h_rotl(x1, r); x1 ^= x0; }
    TH_R(13) TH_R(15) TH_R(26) TH_R(6)
    x0 += k1;  x1 += ks2 + 1u;
    TH_R(17) TH_R(29) TH_R(16) TH_R(24)
    x0 += ks2; x1 += k0 + 2u;
    TH_R(13) TH_R(15) TH_R(26) TH_R(6)
    x0 += k0;  x1 += k1 + 3u;
    TH_R(17) TH_R(29) TH_R(16) TH_R(24)
    x0 += k1;  x1 += ks2 + 4u;
    TH_R(13) TH_R(15) TH_R(26) TH_R(6)
    x0 += ks2; x1 += k0 + 5u;
#undef TH_R
    o0 = x0; o1 = x1;
}
static inline float h_unit_float(unsigned bits) {
    union { unsigned u; float f; } c;
    c.u = (bits >> 9) | 0x3f800000u;
    return c.f - 1.0f;
}

// ---------------------------------------------------------------------------
// tf32 split-compensated NT GEMM, register-side hi/lo split.
// C[m,n] = scale*sum_k A[m,k]*B[n,k] (+bias[n]); A,B row-major k-contiguous.
// OUT_T: write transposed per 512-batch. Tile 128x128, BK=8, 256 thr, 2 blk/SM.
// ---------------------------------------------------------------------------
__device__ __forceinline__ void mma_tf32(float c[4], const uint32_t a[4],
                                         uint32_t b0, uint32_t b1) {
    asm volatile(
        "mma.sync.aligned.m16n8k8.row.col.f32.tf32.tf32.f32 "
        "{%0,%1,%2,%3}, {%4,%5,%6,%7}, {%8,%9}, {%0,%1,%2,%3};\n"
        : "+f"(c[0]), "+f"(c[1]), "+f"(c[2]), "+f"(c[3])
        : "r"(a[0]), "r"(a[1]), "r"(a[2]), "r"(a[3]), "r"(b0), "r"(b1));
}
__device__ __forceinline__ void ldsm4(uint32_t r[4], uint32_t saddr) {
    asm volatile("ldmatrix.sync.aligned.m8n8.x4.shared.b16 {%0,%1,%2,%3}, [%4];"
                 : "=r"(r[0]), "=r"(r[1]), "=r"(r[2]), "=r"(r[3]) : "r"(saddr));
}
__device__ __forceinline__ int sw_off(int row, int kq) {
    return row * 8 + ((kq ^ ((row >> 2) & 1)) << 2);
}

template <bool OUT_T>
__global__ __launch_bounds__(256, 2)
void gemm_nt(const float* __restrict__ Ag, const float* __restrict__ Bg,
             const float* __restrict__ bias, float* __restrict__ Cg,
             float scale) {
    __shared__ float sA[2][1024], sB[2][1024];
    const int t = threadIdx.x;
    const int z = blockIdx.z;
    const float* A = Ag + (size_t)z * (kA * kA);
    const float* B = Bg + (size_t)z * (kA * kA);
    float* C = Cg + (size_t)z * (kA * kA);
    const int n0 = blockIdx.x * 128;
    const int m0 = blockIdx.y * 128;

    const int lane = t & 31, wid = t >> 5;
    const int wm = (wid >> 2) * 64, wn = (wid & 3) * 32;
    const int gid = lane >> 2, tig = lane & 3;

    const int wrow = t & 127, wkq = t >> 7;
    const float* Aptr = A + (size_t)(m0 + wrow) * 512 + wkq * 4;
    const float* Bptr = B + (size_t)(n0 + wrow) * 512 + wkq * 4;
    const int wOff = sw_off(wrow, wkq);

    const int q = lane >> 3, rr = lane & 7;
    int aOff[4], bOff[2];
#pragma unroll
    for (int mi = 0; mi < 4; mi++) {
        int m = wm + mi * 16 + (q & 1) * 8 + rr;
        aOff[mi] = sw_off(m, q >> 1) * 4;
    }
#pragma unroll
    for (int p = 0; p < 2; p++) {
        int nrow = wn + (p * 2 + (q >> 1)) * 8 + rr;
        bOff[p] = sw_off(nrow, q & 1) * 4;
    }
    const uint32_t bA = (uint32_t)__cvta_generic_to_shared(&sA[0][0]);
    const uint32_t bB = (uint32_t)__cvta_generic_to_shared(&sB[0][0]);

    float c[4][4][4];
#pragma unroll
    for (int mi = 0; mi < 4; mi++)
#pragma unroll
        for (int ni = 0; ni < 4; ni++)
#pragma unroll
            for (int r = 0; r < 4; r++) c[mi][ni][r] = 0.f;

    float4 ra, rb;
    auto gload = [&](int k0) {
        ra = *reinterpret_cast<const float4*>(Aptr + k0);
        rb = *reinterpret_cast<const float4*>(Bptr + k0);
    };
    auto sts = [&](int buf) {
        *reinterpret_cast<float4*>(&sA[buf][wOff]) = ra;
        *reinterpret_cast<float4*>(&sB[buf][wOff]) = rb;
    };

    gload(0);
    sts(0);
    __syncthreads();

    for (int ks = 0; ks < 64; ks++) {
        const int buf = ks & 1;
        const uint32_t bo = (uint32_t)buf * 4096u;
        if (ks < 63) gload((ks + 1) * 8);

        uint32_t araw[4][4], braw[2][4];
#pragma unroll
        for (int mi = 0; mi < 4; mi++) ldsm4(araw[mi], bA + bo + aOff[mi]);
#pragma unroll
        for (int p = 0; p < 2; p++) ldsm4(braw[p], bB + bo + bOff[p]);

        // register-side hi/lo split
        uint32_t ah[4][4], al[4][4], bh[2][4], bl[2][4];
#pragma unroll
        for (int mi = 0; mi < 4; mi++)
#pragma unroll
            for (int r = 0; r < 4; r++) {
                uint32_t hv = araw[mi][r] & 0xFFFFE000u;
                ah[mi][r] = hv;
                al[mi][r] = __float_as_uint(__uint_as_float(araw[mi][r]) -
                                            __uint_as_float(hv));
            }
#pragma unroll
        for (int p = 0; p < 2; p++)
#pragma unroll
            for (int r = 0; r < 4; r++) {
                uint32_t hv = braw[p][r] & 0xFFFFE000u;
                bh[p][r] = hv;
                bl[p][r] = __float_as_uint(__uint_as_float(braw[p][r]) -
                                           __uint_as_float(hv));
            }

#pragma unroll
        for (int mi = 0; mi < 4; mi++)
#pragma unroll
            for (int ni = 0; ni < 4; ni++) {
                const int p = ni >> 1, s0 = (ni & 1) * 2;
                mma_tf32(c[mi][ni], ah[mi], bh[p][s0], bh[p][s0 + 1]);
                mma_tf32(c[mi][ni], ah[mi], bl[p][s0], bl[p][s0 + 1]);
                mma_tf32(c[mi][ni], al[mi], bh[p][s0], bh[p][s0 + 1]);
            }
        if (ks < 63) {
            sts(buf ^ 1);
            __syncthreads();
        }
    }

#pragma unroll
    for (int mi = 0; mi < 4; mi++) {
#pragma unroll
        for (int ni = 0; ni < 4; ni++) {
            const int gm = m0 + wm + mi * 16 + gid;
            const int gc = n0 + wn + ni * 8 + 2 * tig;
            if (OUT_T) {
                const float bv0 = bias[gc], bv1 = bias[gc + 1];
                float* Cb = C + (size_t)(gm >> 9) * (kA * kA);
                const int j0 = gm & 511, j1 = (gm + 8) & 511;
                Cb[(size_t)gc * 512 + j0]       = c[mi][ni][0] + bv0;
                Cb[(size_t)(gc + 1) * 512 + j0] = c[mi][ni][1] + bv1;
                Cb[(size_t)gc * 512 + j1]       = c[mi][ni][2] + bv0;
                Cb[(size_t)(gc + 1) * 512 + j1] = c[mi][ni][3] + bv1;
            } else {
                float2 o0, o1;
                o0.x = c[mi][ni][0] * scale; o0.y = c[mi][ni][1] * scale;
                o1.x = c[mi][ni][2] * scale; o1.y = c[mi][ni][3] * scale;
                *reinterpret_cast<float2*>(&C[(size_t)gm * 512 + gc]) = o0;
                *reinterpret_cast<float2*>(&C[(size_t)(gm + 8) * 512 + gc]) = o1;
            }
        }
    }
}

// ---------------------------------------------------------------------------
// Vp[b,i] = sum_k V[b,k]*Wv[i,k] + bv[i].  Block per i, warp w -> b=w,w+8.
// ---------------------------------------------------------------------------
__global__ __launch_bounds__(256)
void vp_kernel(const float* __restrict__ V, const float* __restrict__ Wv,
               const float* __restrict__ bv) {
    const int i = blockIdx.x;
    const int w = threadIdx.x >> 5, lane = threadIdx.x & 31;
    const float* wr = Wv + (size_t)i * 512;
    float a0 = 0.f, a1 = 0.f;
#pragma unroll
    for (int cc = 0; cc < 4; cc++) {
        const int k = cc * 128 + lane * 4;
        float4 w4 = *reinterpret_cast<const float4*>(wr + k);
        float4 v0 = *reinterpret_cast<const float4*>(V + w * 512 + k);
        float4 v1 = *reinterpret_cast<const float4*>(V + (w + 8) * 512 + k);
        a0 += w4.x * v0.x + w4.y * v0.y + w4.z * v0.z + w4.w * v0.w;
        a1 += w4.x * v1.x + w4.y * v1.y + w4.z * v1.z + w4.w * v1.w;
    }
    a0 = warpSum(a0); a1 = warpSum(a1);
    if (lane == 0) {
        float b = bv[i];
        g_Vp[w * 512 + i] = a0 + b;
        g_Vp[(w + 8) * 512 + i] = a1 + b;
    }
}

// ---------------------------------------------------------------------------
// Fused kernels — mutate / crossover variants chosen at capture time on host.
// Block 256 thr per (i, b); warp h = head h; 16 j per lane.
// ---------------------------------------------------------------------------
__global__ __launch_bounds__(256)
void fused_mut(unsigned km0, unsigned km1) {
    const int i = blockIdx.x, b = blockIdx.y;
    const int t = threadIdx.x, lane = t & 31, h = t >> 5;
    __shared__ float sv[512], svp[512];

    if (t < 128)
        *reinterpret_cast<float4*>(&sv[t * 4]) =
            *reinterpret_cast<const float4*>(g_am0 + ((size_t)b * kA + i) * kA + t * 4);
    else
        *reinterpret_cast<float4*>(&svp[(t - 128) * 4]) =
            *reinterpret_cast<const float4*>(g_Vp + b * kA + (t - 128) * 4);
    __syncthreads();

    const unsigned base = ((unsigned)(b * 8 + h) << 18) + ((unsigned)i << 9) + (unsigned)lane;
    float s = 0.f, d = 0.f;
#pragma unroll 8
    for (int cc = 0; cc < 16; cc++) {
        const int j = cc * 32 + lane;
        unsigned o0, o1;
        tf2x32(km0, km1, 0u, base + (unsigned)(cc * 32), o0, o1);
        const float e = __expf(sv[j] * mut_factor(o0 ^ o1));
        s += e; d += e * svp[j];
    }
    s = warpSum(s); d = warpSum(d);
    if (lane == 0) g_out3[(b * 8 + h) * kA + i] = d / s;
}

struct CrossArgs { int r1[kB * kH]; int r2[kB * kH]; };

__global__ __launch_bounds__(256)
void fused_cross(CrossArgs args) {
    const int i = blockIdx.x, b = blockIdx.y;
    const int t = threadIdx.x, lane = t & 31, h = t >> 5;
    __shared__ float sv[512], svp[512];

    if (t < 128)
        *reinterpret_cast<float4*>(&sv[t * 4]) =
            *reinterpret_cast<const float4*>(g_am0 + ((size_t)b * kA + i) * kA + t * 4);
    else
        *reinterpret_cast<float4*>(&svp[(t - 128) * 4]) =
            *reinterpret_cast<const float4*>(g_Vp + b * kA + (t - 128) * 4);
    __syncthreads();

    const int bh = b * 8 + h;
    const int r1 = args.r1[bh], r2 = args.r2[bh];
    const int src = (i == r1) ? r2 : (i == r2) ? r1 : i;
    const float* srow = g_am0 + ((size_t)b * kA + src) * kA;
    float s = 0.f, d = 0.f;
#pragma unroll 4
    for (int cc = 0; cc < 16; cc++) {
        const int j = cc * 32 + lane;
        const float v = (src == i || j < kC) ? sv[j] : srow[j];
        const float e = __expf(v);
        s += e; d += e * svp[j];
    }
    s = warpSum(s); d = warpSum(d);
    if (lane == 0) g_out3[bh * kA + i] = d / s;
}

// ---------------------------------------------------------------------------
// y[b,o] = sum_x g_out3[b*4096+x]*WOw[o,x] + WOb[o].
// ---------------------------------------------------------------------------
__global__ __launch_bounds__(256)
void out_proj(const float* __restrict__ WOw, const float* __restrict__ WOb,
              float* __restrict__ y) {
    __shared__ float xs[16][516];
    const int t = threadIdx.x;
    const int o_l = t >> 4, bq = t & 15;
    const int o = blockIdx.x * 16 + o_l;
    float acc = 0.f;

    for (int ch = 0; ch < 8; ch++) {
#pragma unroll
        for (int l = 0; l < 8; l++) {
            int idx = t + l * 256;
            int row = idx >> 7, c4 = idx & 127;
            *reinterpret_cast<float4*>(&xs[row][c4 * 4]) =
                *reinterpret_cast<const float4*>(g_out3 + row * 4096 + ch * 512 + c4 * 4);
        }
        __syncthreads();
        const float4* Wp = reinterpret_cast<const float4*>(WOw + (size_t)o * 4096 + ch * 512);
#pragma unroll 8
        for (int k4 = 0; k4 < 128; k4++) {
            float4 w4 = Wp[k4];
            float4 x4 = *reinterpret_cast<const float4*>(&xs[bq][k4 * 4]);
            acc += w4.x * x4.x + w4.y * x4.y + w4.z * x4.z + w4.w * x4.w;
        }
        __syncthreads();
    }
    y[bq * 512 + o] = acc + WOb[o];
}

// ---------------------------------------------------------------------------
// Launch — all PRNG key derivation happens HERE on the host (key=42 is a
// constant in the reference), so the device never branches on it.
// ---------------------------------------------------------------------------
extern "C" void kernel_launch(void* const* d_in, const int* in_sizes, int n_in,
                              void* d_out, int out_size) {
    const float* Q   = (const float*)d_in[0];
    const float* K   = (const float*)d_in[1];
    const float* V   = (const float*)d_in[2];
    const float* WQw = (const float*)d_in[3];
    const float* WQb = (const float*)d_in[4];
    const float* WKw = (const float*)d_in[5];
    const float* WKb = (const float*)d_in[6];
    const float* WVw = (const float*)d_in[7];
    const float* WVb = (const float*)d_in[8];
    const float* WOw = (const float*)d_in[9];
    const float* WOb = (const float*)d_in[10];
    float* y = (float*)d_out;

    float* dQpT; cudaGetSymbolAddress((void**)&dQpT, g_QpT);
    float* dKpT; cudaGetSymbolAddress((void**)&dKpT, g_KpT);
    float* dam;  cudaGetSymbolAddress((void**)&dam,  g_am0);

    // --- host PRNG (deterministic, key = 42) ---
    unsigned kp0, kp1, km0, km1, kr10, kr11, kr20, kr21;
    h_tf2x32(0u, 42u, 0u, 0u, kp0, kp1);
    h_tf2x32(0u, 42u, 0u, 1u, km0, km1);
    h_tf2x32(0u, 42u, 0u, 2u, kr10, kr11);
    h_tf2x32(0u, 42u, 0u, 3u, kr20, kr21);
    unsigned o0, o1;
    h_tf2x32(kp0, kp1, 0u, 0u, o0, o1);
    const bool mutate = (h_unit_float(o0 ^ o1) <= 0.6f);
    CrossArgs ca;
    if (!mutate) {
        unsigned a0, a1;
        h_tf2x32(kr10, kr11, 0u, 1u, a0, a1);
        for (int t = 0; t < kB * kH; t++) {
            h_tf2x32(a0, a1, 0u, (unsigned)t, o0, o1);
            ca.r1[t] = (int)((o0 ^ o1) & 511u);
        }
        h_tf2x32(kr20, kr21, 0u, 1u, a0, a1);
        for (int t = 0; t < kB * kH; t++) {
            h_tf2x32(a0, a1, 0u, (unsigned)t, o0, o1);
            ca.r2[t] = (int)((o0 ^ o1) & 511u);
        }
    }

    vp_kernel<<<512, 256>>>(V, WVw, WVb);
    gemm_nt<true><<<dim3(4, 64, 1), 256>>>(Q, WQw, WQb, dQpT, 1.0f);
    gemm_nt<true><<<dim3(4, 64, 1), 256>>>(K, WKw, WKb, dKpT, 1.0f);
    gemm_nt<false><<<dim3(4, 4, 16), 256>>>(dQpT, dKpT, nullptr, dam,
                                            1.0f / sqrtf(8.0f));
    if (mutate)
        fused_mut<<<dim3(512, 16), 256>>>(km0, km1);
    else
        fused_cross<<<dim3(512, 16), 256>>>(ca);
    out_proj<<<32, 256>>>(WOw, WOb, y);
}

// round 7
// speedup vs baseline: 1.6869x; 1.0702x over previous
#include <cuda_runtime.h>
#include <cstdint>

#define kB 16
#define kH 8
#define kA 512
#define kC 359   /* A - int(A*0.3) */

// ---------------------------------------------------------------------------
// Scratch (device globals)
// ---------------------------------------------------------------------------
__device__ float g_QpT[kB * kA * kA];      // (B, A, A)  QpT[b,i,j] (j contiguous)
__device__ float g_KpT[kB * kA * kA];      // (B, A, A)  KpT[b,n,j]
__device__ float g_am0[kB * kA * kA];      // (B, A, A)  am0[b,i,n] (scaled)
__device__ float g_Vp[kB * kA];
__device__ float g_out3[kB * kH * kA];     // [bh*512 + i]

// ---------------------------------------------------------------------------
// Threefry2x32 — device (mutation factors) + host (keys)
// ---------------------------------------------------------------------------
__device__ __forceinline__ void tf2x32(unsigned k0, unsigned k1,
                                       unsigned x0, unsigned x1,
                                       unsigned &o0, unsigned &o1) {
    unsigned ks2 = k0 ^ k1 ^ 0x1BD11BDAu;
    x0 += k0; x1 += k1;
#define TF_R(r) { x0 += x1; x1 = __funnelshift_l(x1, x1, r); x1 ^= x0; }
    TF_R(13) TF_R(15) TF_R(26) TF_R(6)
    x0 += k1;  x1 += ks2 + 1u;
    TF_R(17) TF_R(29) TF_R(16) TF_R(24)
    x0 += ks2; x1 += k0 + 2u;
    TF_R(13) TF_R(15) TF_R(26) TF_R(6)
    x0 += k0;  x1 += k1 + 3u;
    TF_R(17) TF_R(29) TF_R(16) TF_R(24)
    x0 += k1;  x1 += ks2 + 4u;
    TF_R(13) TF_R(15) TF_R(26) TF_R(6)
    x0 += ks2; x1 += k0 + 5u;
#undef TF_R
    o0 = x0; o1 = x1;
}
__device__ __forceinline__ float unit_float(unsigned bits) {
    return __uint_as_float((bits >> 9) | 0x3f800000u) - 1.0f;
}
__device__ __forceinline__ float mut_factor(unsigned bits) {
    const float mn = 0.7f, mx = 1.3f;
    return fmaxf(mn, unit_float(bits) * (mx - mn) + mn);
}
__device__ __forceinline__ float warpSum(float v) {
#pragma unroll
    for (int o = 16; o > 0; o >>= 1) v += __shfl_xor_sync(0xffffffffu, v, o);
    return v;
}

static inline unsigned h_rotl(unsigned v, int r) { return (v << r) | (v >> (32 - r)); }
static void h_tf2x32(unsigned k0, unsigned k1, unsigned x0, unsigned x1,
                     unsigned &o0, unsigned &o1) {
    unsigned ks2 = k0 ^ k1 ^ 0x1BD11BDAu;
    x0 += k0; x1 += k1;
#define TH_R(r) { x0 += x1; x1 = h_rotl(x1, r); x1 ^= x0; }
    TH_R(13) TH_R(15) TH_R(26) TH_R(6)
    x0 += k1;  x1 += ks2 + 1u;
    TH_R(17) TH_R(29) TH_R(16) TH_R(24)
    x0 += ks2; x1 += k0 + 2u;
    TH_R(13) TH_R(15) TH_R(26) TH_R(6)
    x0 += k0;  x1 += k1 + 3u;
    TH_R(17) TH_R(29) TH_R(16) TH_R(24)
    x0 += k1;  x1 += ks2 + 4u;
    TH_R(13) TH_R(15) TH_R(26) TH_R(6)
    x0 += ks2; x1 += k0 + 5u;
#undef TH_R
    o0 = x0; o1 = x1;
}
static inline float h_unit_float(unsigned bits) {
    union { unsigned u; float f; } c;
    c.u = (bits >> 9) | 0x3f800000u;
    return c.f - 1.0f;
}

// ---------------------------------------------------------------------------
// tf32 split-compensated NT GEMM, register-side hi/lo split.
// 128x128 tile, BK=8, 128 threads (4 warps, 64x64 warp tile), 2 CTA/SM.
// OUT_T (projections): grid.z selects {Q,WQ}->QpT vs {K,WK}->KpT, output
//   written transposed per 512-row batch.
// !OUT_T (am0): grid.z = batch, C = scale * A B^T (row-major out).
// ---------------------------------------------------------------------------
__device__ __forceinline__ void mma_tf32(float c[4], const uint32_t a[4],
                                         uint32_t b0, uint32_t b1) {
    asm volatile(
        "mma.sync.aligned.m16n8k8.row.col.f32.tf32.tf32.f32 "
        "{%0,%1,%2,%3}, {%4,%5,%6,%7}, {%8,%9}, {%0,%1,%2,%3};\n"
        : "+f"(c[0]), "+f"(c[1]), "+f"(c[2]), "+f"(c[3])
        : "r"(a[0]), "r"(a[1]), "r"(a[2]), "r"(a[3]), "r"(b0), "r"(b1));
}
__device__ __forceinline__ void ldsm4(uint32_t r[4], uint32_t saddr) {
    asm volatile("ldmatrix.sync.aligned.m8n8.x4.shared.b16 {%0,%1,%2,%3}, [%4];"
                 : "=r"(r[0]), "=r"(r[1]), "=r"(r[2]), "=r"(r[3]) : "r"(saddr));
}
__device__ __forceinline__ int sw_off(int row, int kq) {
    return row * 8 + ((kq ^ ((row >> 2) & 1)) << 2);
}

template <bool OUT_T>
__global__ __launch_bounds__(128, 2)
void gemm_nt(const float* __restrict__ A0, const float* __restrict__ A1,
             const float* __restrict__ W0, const float* __restrict__ W1,
             const float* __restrict__ bias0, const float* __restrict__ bias1,
             float* __restrict__ C0, float* __restrict__ C1, float scale) {
    __shared__ float sA[2][1024], sB[2][1024];
    const int t = threadIdx.x;

    const float* A;
    const float* B;
    const float* bias;
    float* C;
    if (OUT_T) {
        const int sel = blockIdx.z;
        A = sel ? A1 : A0;
        B = sel ? W1 : W0;
        bias = sel ? bias1 : bias0;
        C = sel ? C1 : C0;
    } else {
        const int z = blockIdx.z;
        A = A0 + (size_t)z * (kA * kA);
        B = W0 + (size_t)z * (kA * kA);
        bias = nullptr;
        C = C0 + (size_t)z * (kA * kA);
    }
    const int n0 = blockIdx.x * 128;
    const int m0 = blockIdx.y * 128;

    const int lane = t & 31, wid = t >> 5;
    const int wm = (wid >> 1) * 64, wn = (wid & 1) * 64;
    const int gid = lane >> 2, tig = lane & 3;

    // writer: thread t owns row t of both tiles (8 floats = 2 granules)
    const float* Aptr = A + (size_t)(m0 + t) * 512;
    const float* Bptr = B + (size_t)(n0 + t) * 512;
    const int wOff0 = sw_off(t, 0), wOff1 = sw_off(t, 1);

    // ldmatrix source offsets (bytes); q = lane>>3 selects 8x8 sub-matrix
    const int q = lane >> 3, rr = lane & 7;
    int aOff[4], bOff[4];
#pragma unroll
    for (int mi = 0; mi < 4; mi++) {
        int m = wm + mi * 16 + (q & 1) * 8 + rr;
        aOff[mi] = sw_off(m, q >> 1) * 4;
    }
#pragma unroll
    for (int p = 0; p < 4; p++) {
        int nrow = wn + (p * 2 + (q >> 1)) * 8 + rr;
        bOff[p] = sw_off(nrow, q & 1) * 4;
    }
    const uint32_t bA = (uint32_t)__cvta_generic_to_shared(&sA[0][0]);
    const uint32_t bB = (uint32_t)__cvta_generic_to_shared(&sB[0][0]);

    float c[4][8][4];
#pragma unroll
    for (int mi = 0; mi < 4; mi++)
#pragma unroll
        for (int ni = 0; ni < 8; ni++)
#pragma unroll
            for (int r = 0; r < 4; r++) c[mi][ni][r] = 0.f;

    float4 ra0, ra1, rb0, rb1;
    auto gload = [&](int k0) {
        ra0 = *reinterpret_cast<const float4*>(Aptr + k0);
        ra1 = *reinterpret_cast<const float4*>(Aptr + k0 + 4);
        rb0 = *reinterpret_cast<const float4*>(Bptr + k0);
        rb1 = *reinterpret_cast<const float4*>(Bptr + k0 + 4);
    };
    auto sts = [&](int buf) {
        *reinterpret_cast<float4*>(&sA[buf][wOff0]) = ra0;
        *reinterpret_cast<float4*>(&sA[buf][wOff1]) = ra1;
        *reinterpret_cast<float4*>(&sB[buf][wOff0]) = rb0;
        *reinterpret_cast<float4*>(&sB[buf][wOff1]) = rb1;
    };

    gload(0);
    sts(0);
    __syncthreads();

    for (int ks = 0; ks < 64; ks++) {
        const int buf = ks & 1;
        const uint32_t bo = (uint32_t)buf * 4096u;
        if (ks < 63) gload((ks + 1) * 8);

        uint32_t al[4][4], bl[4][4];     // raw load, becomes lo after split
        uint32_t ah[4][4], bh[4][4];
#pragma unroll
        for (int mi = 0; mi < 4; mi++) ldsm4(al[mi], bA + bo + aOff[mi]);
#pragma unroll
        for (int p = 0; p < 4; p++) ldsm4(bl[p], bB + bo + bOff[p]);

#pragma unroll
        for (int mi = 0; mi < 4; mi++)
#pragma unroll
            for (int r = 0; r < 4; r++) {
                uint32_t hv = al[mi][r] & 0xFFFFE000u;
                ah[mi][r] = hv;
                al[mi][r] = __float_as_uint(__uint_as_float(al[mi][r]) -
                                            __uint_as_float(hv));
            }
#pragma unroll
        for (int p = 0; p < 4; p++)
#pragma unroll
            for (int r = 0; r < 4; r++) {
                uint32_t hv = bl[p][r] & 0xFFFFE000u;
                bh[p][r] = hv;
                bl[p][r] = __float_as_uint(__uint_as_float(bl[p][r]) -
                                           __uint_as_float(hv));
            }

#pragma unroll
        for (int mi = 0; mi < 4; mi++)
#pragma unroll
            for (int ni = 0; ni < 8; ni++) {
                const int p = ni >> 1, s0 = (ni & 1) * 2;
                mma_tf32(c[mi][ni], ah[mi], bh[p][s0], bh[p][s0 + 1]);
                mma_tf32(c[mi][ni], ah[mi], bl[p][s0], bl[p][s0 + 1]);
                mma_tf32(c[mi][ni], al[mi], bh[p][s0], bh[p][s0 + 1]);
            }
        if (ks < 63) {
            sts(buf ^ 1);
            __syncthreads();
        }
    }

#pragma unroll
    for (int mi = 0; mi < 4; mi++) {
#pragma unroll
        for (int ni = 0; ni < 8; ni++) {
            const int gm = m0 + wm + mi * 16 + gid;
            const int gc = n0 + wn + ni * 8 + 2 * tig;
            if (OUT_T) {
                const float bv0 = bias[gc], bv1 = bias[gc + 1];
                float* Cb = C + (size_t)(gm >> 9) * (kA * kA);
                const int j0 = gm & 511, j1 = (gm + 8) & 511;
                Cb[(size_t)gc * 512 + j0]       = c[mi][ni][0] + bv0;
                Cb[(size_t)(gc + 1) * 512 + j0] = c[mi][ni][1] + bv1;
                Cb[(size_t)gc * 512 + j1]       = c[mi][ni][2] + bv0;
                Cb[(size_t)(gc + 1) * 512 + j1] = c[mi][ni][3] + bv1;
            } else {
                float2 o0, o1;
                o0.x = c[mi][ni][0] * scale; o0.y = c[mi][ni][1] * scale;
                o1.x = c[mi][ni][2] * scale; o1.y = c[mi][ni][3] * scale;
                *reinterpret_cast<float2*>(&C[(size_t)gm * 512 + gc]) = o0;
                *reinterpret_cast<float2*>(&C[(size_t)(gm + 8) * 512 + gc]) = o1;
            }
        }
    }
}

// ---------------------------------------------------------------------------
// Vp[b,i] = sum_k V[b,k]*Wv[i,k] + bv[i].  Block per i, warp w -> b=w,w+8.
// ---------------------------------------------------------------------------
__global__ __launch_bounds__(256)
void vp_kernel(const float* __restrict__ V, const float* __restrict__ Wv,
               const float* __restrict__ bv) {
    const int i = blockIdx.x;
    const int w = threadIdx.x >> 5, lane = threadIdx.x & 31;
    const float* wr = Wv + (size_t)i * 512;
    float a0 = 0.f, a1 = 0.f;
#pragma unroll
    for (int cc = 0; cc < 4; cc++) {
        const int k = cc * 128 + lane * 4;
        float4 w4 = *reinterpret_cast<const float4*>(wr + k);
        float4 v0 = *reinterpret_cast<const float4*>(V + w * 512 + k);
        float4 v1 = *reinterpret_cast<const float4*>(V + (w + 8) * 512 + k);
        a0 += w4.x * v0.x + w4.y * v0.y + w4.z * v0.z + w4.w * v0.w;
        a1 += w4.x * v1.x + w4.y * v1.y + w4.z * v1.z + w4.w * v1.w;
    }
    a0 = warpSum(a0); a1 = warpSum(a1);
    if (lane == 0) {
        float b = bv[i];
        g_Vp[w * 512 + i] = a0 + b;
        g_Vp[(w + 8) * 512 + i] = a1 + b;
    }
}

// ---------------------------------------------------------------------------
// Fused kernels — mutate / crossover chosen at capture time on host.
// ---------------------------------------------------------------------------
__global__ __launch_bounds__(256)
void fused_mut(unsigned km0, unsigned km1) {
    const int i = blockIdx.x, b = blockIdx.y;
    const int t = threadIdx.x, lane = t & 31, h = t >> 5;
    __shared__ float sv[512], svp[512];

    if (t < 128)
        *reinterpret_cast<float4*>(&sv[t * 4]) =
            *reinterpret_cast<const float4*>(g_am0 + ((size_t)b * kA + i) * kA + t * 4);
    else
        *reinterpret_cast<float4*>(&svp[(t - 128) * 4]) =
            *reinterpret_cast<const float4*>(g_Vp + b * kA + (t - 128) * 4);
    __syncthreads();

    const unsigned base = ((unsigned)(b * 8 + h) << 18) + ((unsigned)i << 9) + (unsigned)lane;
    float s = 0.f, d = 0.f;
#pragma unroll 8
    for (int cc = 0; cc < 16; cc++) {
        const int j = cc * 32 + lane;
        unsigned o0, o1;
        tf2x32(km0, km1, 0u, base + (unsigned)(cc * 32), o0, o1);
        const float e = __expf(sv[j] * mut_factor(o0 ^ o1));
        s += e; d += e * svp[j];
    }
    s = warpSum(s); d = warpSum(d);
    if (lane == 0) g_out3[(b * 8 + h) * kA + i] = d / s;
}

struct CrossArgs { int r1[kB * kH]; int r2[kB * kH]; };

__global__ __launch_bounds__(256)
void fused_cross(CrossArgs args) {
    const int i = blockIdx.x, b = blockIdx.y;
    const int t = threadIdx.x, lane = t & 31, h = t >> 5;
    __shared__ float sv[512], svp[512];

    if (t < 128)
        *reinterpret_cast<float4*>(&sv[t * 4]) =
            *reinterpret_cast<const float4*>(g_am0 + ((size_t)b * kA + i) * kA + t * 4);
    else
        *reinterpret_cast<float4*>(&svp[(t - 128) * 4]) =
            *reinterpret_cast<const float4*>(g_Vp + b * kA + (t - 128) * 4);
    __syncthreads();

    const int bh = b * 8 + h;
    const int r1 = args.r1[bh], r2 = args.r2[bh];
    const int src = (i == r1) ? r2 : (i == r2) ? r1 : i;
    const float* srow = g_am0 + ((size_t)b * kA + src) * kA;
    float s = 0.f, d = 0.f;
#pragma unroll 4
    for (int cc = 0; cc < 16; cc++) {
        const int j = cc * 32 + lane;
        const float v = (src == i || j < kC) ? sv[j] : srow[j];
        const float e = __expf(v);
        s += e; d += e * svp[j];
    }
    s = warpSum(s); d = warpSum(d);
    if (lane == 0) g_out3[bh * kA + i] = d / s;
}

// ---------------------------------------------------------------------------
// y[b,o] = sum_x g_out3[b*4096+x]*WOw[o,x] + WOb[o].
// ---------------------------------------------------------------------------
__global__ __launch_bounds__(256)
void out_proj(const float* __restrict__ WOw, const float* __restrict__ WOb,
              float* __restrict__ y) {
    __shared__ float xs[16][516];
    const int t = threadIdx.x;
    const int o_l = t >> 4, bq = t & 15;
    const int o = blockIdx.x * 16 + o_l;
    float acc = 0.f;

    for (int ch = 0; ch < 8; ch++) {
#pragma unroll
        for (int l = 0; l < 8; l++) {
            int idx = t + l * 256;
            int row = idx >> 7, c4 = idx & 127;
            *reinterpret_cast<float4*>(&xs[row][c4 * 4]) =
                *reinterpret_cast<const float4*>(g_out3 + row * 4096 + ch * 512 + c4 * 4);
        }
        __syncthreads();
        const float4* Wp = reinterpret_cast<const float4*>(WOw + (size_t)o * 4096 + ch * 512);
#pragma unroll 8
        for (int k4 = 0; k4 < 128; k4++) {
            float4 w4 = Wp[k4];
            float4 x4 = *reinterpret_cast<const float4*>(&xs[bq][k4 * 4]);
            acc += w4.x * x4.x + w4.y * x4.y + w4.z * x4.z + w4.w * x4.w;
        }
        __syncthreads();
    }
    y[bq * 512 + o] = acc + WOb[o];
}

// ---------------------------------------------------------------------------
// Launch — host PRNG; merged projection GEMM launch
// ---------------------------------------------------------------------------
extern "C" void kernel_launch(void* const* d_in, const int* in_sizes, int n_in,
                              void* d_out, int out_size) {
    const float* Q   = (const float*)d_in[0];
    const float* K   = (const float*)d_in[1];
    const float* V   = (const float*)d_in[2];
    const float* WQw = (const float*)d_in[3];
    const float* WQb = (const float*)d_in[4];
    const float* WKw = (const float*)d_in[5];
    const float* WKb = (const float*)d_in[6];
    const float* WVw = (const float*)d_in[7];
    const float* WVb = (const float*)d_in[8];
    const float* WOw = (const float*)d_in[9];
    const float* WOb = (const float*)d_in[10];
    float* y = (float*)d_out;

    float* dQpT; cudaGetSymbolAddress((void**)&dQpT, g_QpT);
    float* dKpT; cudaGetSymbolAddress((void**)&dKpT, g_KpT);
    float* dam;  cudaGetSymbolAddress((void**)&dam,  g_am0);

    // --- host PRNG (deterministic, key = 42) ---
    unsigned kp0, kp1, km0, km1, kr10, kr11, kr20, kr21;
    h_tf2x32(0u, 42u, 0u, 0u, kp0, kp1);
    h_tf2x32(0u, 42u, 0u, 1u, km0, km1);
    h_tf2x32(0u, 42u, 0u, 2u, kr10, kr11);
    h_tf2x32(0u, 42u, 0u, 3u, kr20, kr21);
    unsigned o0, o1;
    h_tf2x32(kp0, kp1, 0u, 0u, o0, o1);
    const bool mutate = (h_unit_float(o0 ^ o1) <= 0.6f);
    CrossArgs ca;
    if (!mutate) {
        unsigned a0, a1;
        h_tf2x32(kr10, kr11, 0u, 1u, a0, a1);
        for (int t = 0; t < kB * kH; t++) {
            h_tf2x32(a0, a1, 0u, (unsigned)t, o0, o1);
            ca.r1[t] = (int)((o0 ^ o1) & 511u);
        }
        h_tf2x32(kr20, kr21, 0u, 1u, a0, a1);
        for (int t = 0; t < kB * kH; t++) {
            h_tf2x32(a0, a1, 0u, (unsigned)t, o0, o1);
            ca.r2[t] = (int)((o0 ^ o1) & 511u);
        }
    }

    vp_kernel<<<512, 256>>>(V, WVw, WVb);
    // merged Q/K projections: grid.z in {0 -> Q, 1 -> K}
    gemm_nt<true><<<dim3(4, 64, 2), 128>>>(Q, K, WQw, WKw, WQb, WKb,
                                           dQpT, dKpT, 1.0f);
    // am0[b] = (1/sqrt8) QpT[b] @ KpT[b]^T
    gemm_nt<false><<<dim3(4, 4, 16), 128>>>(dQpT, nullptr, dKpT, nullptr,
                                            nullptr, nullptr, dam, nullptr,
                                            1.0f / sqrtf(8.0f));
    if (mutate)
        fused_mut<<<dim3(512, 16), 256>>>(km0, km1);
    else
        fused_cross<<<dim3(512, 16), 256>>>(ca);
    out_proj<<<32, 256>>>(WOw, WOb, y);
}